// round 15
// baseline (speedup 1.0000x reference)
#include <cuda_runtime.h>
#include <cuda_bf16.h>
#include <cuda_fp16.h>
#include <cstdint>

// ---------------------------------------------------------------------------
// WMSA, b=4, H=W=256, c=256, WS=8, HEAD_DIM=32.
// R15: GEMM CTAs widened to 128x128 (256 thr, 8 warps of 64x32, 2x4) to halve
// A-fragment L2 traffic (qkv was going L2-bound at 50%). qkv single-term
// fp16; out_gemm 2-term; attention 2-term QK/PV. Layouts = R14 verified.
// ---------------------------------------------------------------------------

#define QKV_SCALE 0.1767766952966369f   // 32^-0.5

// Fragment arrays (fp16). frag = 256 half = 128 u32 = 32 uint4 = 512 B.
__device__ __align__(16) __half g_xf_hi[67108864];                    // x A-frags (hi only)
__device__ __align__(16) __half g_wqf_hi[196608];                     // w_qkv B-frags (hi only)
__device__ __align__(16) __half g_wof_hi[65536];                      // w_out B-frags (hi only)
__device__ __align__(16) __half g_qf_hi[67108864], g_qf_lo[67108864]; // per blk Q A-frags
__device__ __align__(16) __half g_kf_hi[67108864];                    // per blk K B-frags (hi only)
__device__ __align__(16) __half g_vf_hi[67108864];                    // per blk VT B-frags (hi only)
__device__ __align__(16) __half g_af_hi[67108864], g_af_lo[67108864]; // attn-out A-frags

// ---------------- helpers ----------------
__device__ __forceinline__ uint32_t smem_u32(const void* p) {
    uint32_t a;
    asm("{ .reg .u64 t; cvta.to.shared.u64 t, %1; cvt.u32.u64 %0, t; }"
        : "=r"(a) : "l"(p));
    return a;
}
__device__ __forceinline__ void mma_f16(float* c, const uint32_t* a,
                                        uint32_t b0, uint32_t b1) {
    asm volatile(
        "mma.sync.aligned.m16n8k16.row.col.f32.f16.f16.f32 "
        "{%0,%1,%2,%3}, {%4,%5,%6,%7}, {%8,%9}, {%0,%1,%2,%3};"
        : "+f"(c[0]), "+f"(c[1]), "+f"(c[2]), "+f"(c[3])
        : "r"(a[0]), "r"(a[1]), "r"(a[2]), "r"(a[3]), "r"(b0), "r"(b1));
}
// fp16 split: h = rn(a), l = rn(a - h). Packs two values.
__device__ __forceinline__ void split2(float a, float b, uint32_t& h, uint32_t& l) {
    __half ha = __float2half_rn(a), hb = __float2half_rn(b);
    h = (uint32_t)__half_as_ushort(ha) | ((uint32_t)__half_as_ushort(hb) << 16);
    __half la = __float2half_rn(a - __half2float(ha));
    __half lb = __float2half_rn(b - __half2float(hb));
    l = (uint32_t)__half_as_ushort(la) | ((uint32_t)__half_as_ushort(lb) << 16);
}
// hi-only convert
__device__ __forceinline__ uint32_t cvt2(float a, float b) {
    return (uint32_t)__half_as_ushort(__float2half_rn(a)) |
           ((uint32_t)__half_as_ushort(__float2half_rn(b)) << 16);
}
__device__ __forceinline__ void cp16(uint32_t dst, const void* src) {
    asm volatile("cp.async.cg.shared.global [%0], [%1], 16;" :: "r"(dst), "l"(src));
}

// ---------------------------------------------------------------------------
// cvt_x: gathered (roll+window) tokens -> A-frags (hi only).
// ---------------------------------------------------------------------------
__global__ __launch_bounds__(256) void cvt_x(const float* __restrict__ x) {
    const int gid  = blockIdx.x * 256 + threadIdx.x;
    const int lane = gid & 31;
    const int f    = gid >> 5;          // tf*16 + kf
    const int kf   = f & 15, tf = f >> 4;
    const int r    = lane >> 2;
    const int c0   = kf * 16 + 2 * (lane & 3);
    int t = tf * 16 + r;
    const float* row0; const float* row1;
    {
        int bi = t >> 16, rem = t & 65535, win = rem >> 6, p = rem & 63;
        int hh = (((win >> 5) << 3) + (p >> 3) + 4) & 255;
        int ww = (((win & 31) << 3) + (p & 7) + 4) & 255;
        row0 = x + ((((size_t)bi << 8) + hh) * 256 + ww) * 256;
        t += 8;
        bi = t >> 16; rem = t & 65535; win = rem >> 6; p = rem & 63;
        hh = (((win >> 5) << 3) + (p >> 3) + 4) & 255;
        ww = (((win & 31) << 3) + (p & 7) + 4) & 255;
        row1 = x + ((((size_t)bi << 8) + hh) * 256 + ww) * 256;
    }
    float2 v00 = *(const float2*)(row0 + c0);
    float2 v10 = *(const float2*)(row1 + c0);
    float2 v01 = *(const float2*)(row0 + c0 + 8);
    float2 v11 = *(const float2*)(row1 + c0 + 8);
    uint4 h;
    h.x = cvt2(v00.x, v00.y);
    h.y = cvt2(v10.x, v10.y);
    h.z = cvt2(v01.x, v01.y);
    h.w = cvt2(v11.x, v11.y);
    ((uint4*)g_xf_hi)[(size_t)f * 32 + lane] = h;
}

// cvt weights -> B-frags, hi only.
__global__ __launch_bounds__(256) void cvt_w(const float* __restrict__ w,
                                             __half* __restrict__ hi) {
    const int gid  = blockIdx.x * 256 + threadIdx.x;
    const int lane = gid & 31;
    const int f    = gid >> 5;          // nf*16 + kf
    const int kf   = f & 15, nf = f >> 4;
    const int r    = lane >> 2;
    const int c0   = kf * 16 + 2 * (lane & 3);
    const float* row0 = w + (size_t)(nf * 16 + r) * 256;
    const float* row1 = row0 + 8 * 256;
    float2 v00 = *(const float2*)(row0 + c0);
    float2 v10 = *(const float2*)(row1 + c0);
    float2 v01 = *(const float2*)(row0 + c0 + 8);
    float2 v11 = *(const float2*)(row1 + c0 + 8);
    uint4 h;
    h.x = cvt2(v00.x, v00.y);
    h.y = cvt2(v10.x, v10.y);
    h.z = cvt2(v01.x, v01.y);
    h.w = cvt2(v11.x, v11.y);
    ((uint4*)hi)[(size_t)f * 32 + lane] = h;
}

// ---------------------------------------------------------------------------
// Single-term pipelined mainloop (qkv). CTA 128x128, 256 thr, warps 2x4 of
// 64x32. Stage = 16 frags (A-hi 0-7, B-hi 8-15) = 8 KB; 3 stages = 24 KB.
// ---------------------------------------------------------------------------
struct GemmPtrs1 { const char *ah, *bh; };

__device__ __forceinline__ void issue_stage1(const GemmPtrs1& g, int tfb, int nfb,
                                             int kf, uint32_t smem_base, int tid) {
    const int chunk = tid & 31;
    const int g0    = tid >> 5;          // 0..7
    const uint32_t dbase = smem_base + (kf % 3) * 8192 + chunk * 16;
#pragma unroll
    for (int r = 0; r < 2; r++) {
        const int slot = g0 + 8 * r;
        const char* src;
        if (slot < 8)
            src = g.ah + ((size_t)((tfb + slot) * 16 + kf)) * 512 + chunk * 16;
        else
            src = g.bh + ((size_t)((nfb + slot - 8) * 16 + kf)) * 512 + chunk * 16;
        cp16(dbase + slot * 512, src);
    }
    asm volatile("cp.async.commit_group;" ::: "memory");
}

__device__ __forceinline__ void gemm_mainloop1(const GemmPtrs1& g, int tfb, int nfb,
                                               uint4* smem, int tid,
                                               int warpM, int warpN, int lane,
                                               float acc[4][4][4]) {
    const uint32_t smem_base = smem_u32(smem);
    issue_stage1(g, tfb, nfb, 0, smem_base, tid);
    issue_stage1(g, tfb, nfb, 1, smem_base, tid);

#pragma unroll
    for (int kf = 0; kf < 16; kf++) {
        if (kf < 14)
            asm volatile("cp.async.wait_group 1;" ::: "memory");
        else
            asm volatile("cp.async.wait_group 0;" ::: "memory");
        __syncthreads();
        if (kf < 14) issue_stage1(g, tfb, nfb, kf + 2, smem_base, tid);

        const uint4* sb = smem + (kf % 3) * 512;
        uint4 Ah[4], Bh[2];
#pragma unroll
        for (int mt = 0; mt < 4; mt++)
            Ah[mt] = sb[(warpM * 4 + mt) * 32 + lane];
#pragma unroll
        for (int nb = 0; nb < 2; nb++)
            Bh[nb] = sb[(8 + warpN * 2 + nb) * 32 + lane];
#pragma unroll
        for (int mt = 0; mt < 4; mt++)
#pragma unroll
            for (int nt = 0; nt < 4; nt++) {
                const uint4& B = Bh[nt >> 1];
                mma_f16(acc[mt][nt], (const uint32_t*)&Ah[mt],
                        (nt & 1) ? B.y : B.x, (nt & 1) ? B.w : B.z);
            }
    }
}

// ---------------------------------------------------------------------------
// Two-term pipelined mainloop (out_gemm). CTA 128x128, 256 thr. Stage =
// 24 frags (A-hi 0-7, A-lo 8-15, B-hi 16-23) = 12 KB; 3 stages = 36 KB.
// ---------------------------------------------------------------------------
struct GemmPtrs { const char *ah, *al, *bh; };

__device__ __forceinline__ void issue_stage(const GemmPtrs& g, int tfb, int nfb,
                                            int kf, uint32_t smem_base, int tid) {
    const int chunk = tid & 31;
    const int g0    = tid >> 5;          // 0..7
    const uint32_t dbase = smem_base + (kf % 3) * 12288 + chunk * 16;
#pragma unroll
    for (int r = 0; r < 3; r++) {
        const int slot = g0 + 8 * r;
        const char* src;
        if (slot < 8)
            src = g.ah + ((size_t)((tfb + slot) * 16 + kf)) * 512 + chunk * 16;
        else if (slot < 16)
            src = g.al + ((size_t)((tfb + slot - 8) * 16 + kf)) * 512 + chunk * 16;
        else
            src = g.bh + ((size_t)((nfb + slot - 16) * 16 + kf)) * 512 + chunk * 16;
        cp16(dbase + slot * 512, src);
    }
    asm volatile("cp.async.commit_group;" ::: "memory");
}

__device__ __forceinline__ void gemm_mainloop(const GemmPtrs& g, int tfb, int nfb,
                                              uint4* smem, int tid,
                                              int warpM, int warpN, int lane,
                                              float acc[4][4][4]) {
    const uint32_t smem_base = smem_u32(smem);
    issue_stage(g, tfb, nfb, 0, smem_base, tid);
    issue_stage(g, tfb, nfb, 1, smem_base, tid);

#pragma unroll
    for (int kf = 0; kf < 16; kf++) {
        if (kf < 14)
            asm volatile("cp.async.wait_group 1;" ::: "memory");
        else
            asm volatile("cp.async.wait_group 0;" ::: "memory");
        __syncthreads();
        if (kf < 14) issue_stage(g, tfb, nfb, kf + 2, smem_base, tid);

        const uint4* sb = smem + (kf % 3) * 768;
        uint4 Ah[4], Bh[2];
#pragma unroll
        for (int mt = 0; mt < 4; mt++)
            Ah[mt] = sb[(warpM * 4 + mt) * 32 + lane];
#pragma unroll
        for (int nb = 0; nb < 2; nb++)
            Bh[nb] = sb[(16 + warpN * 2 + nb) * 32 + lane];
#pragma unroll
        for (int mt = 0; mt < 4; mt++)
#pragma unroll
            for (int nt = 0; nt < 4; nt++) {
                const uint4& B = Bh[nt >> 1];
                mma_f16(acc[mt][nt], (const uint32_t*)&Ah[mt],
                        (nt & 1) ? B.y : B.x, (nt & 1) ? B.w : B.z);
            }
        uint4 Al[4];
#pragma unroll
        for (int mt = 0; mt < 4; mt++)
            Al[mt] = sb[(8 + warpM * 4 + mt) * 32 + lane];
#pragma unroll
        for (int mt = 0; mt < 4; mt++)
#pragma unroll
            for (int nt = 0; nt < 4; nt++) {
                const uint4& B = Bh[nt >> 1];
                mma_f16(acc[mt][nt], (const uint32_t*)&Al[mt],
                        (nt & 1) ? B.y : B.x, (nt & 1) ? B.w : B.z);
            }
    }
}

// ---------------------------------------------------------------------------
// Kernel 1: QKV GEMM (single term). grid (6, 2048): bn = 128-col slab.
// ---------------------------------------------------------------------------
__global__ __launch_bounds__(256)
void qkv_gemm(const float* __restrict__ bias) {
    extern __shared__ __align__(16) uint4 smem[];   // 24 KB
    const int tid = threadIdx.x;
    const int bn = blockIdx.x;   // 0..5
    const int bm = blockIdx.y;   // 0..2047
    const int lane = tid & 31;
    const int wid  = tid >> 5;
    const int warpM = wid & 1;
    const int warpN = wid >> 1;  // 0..3

    float acc[4][4][4];
#pragma unroll
    for (int a = 0; a < 4; a++)
#pragma unroll
        for (int b = 0; b < 4; b++)
#pragma unroll
            for (int cR = 0; cR < 4; cR++) acc[a][b][cR] = 0.f;

    GemmPtrs1 g = { (const char*)g_xf_hi, (const char*)g_wqf_hi };
    gemm_mainloop1(g, bm * 8, bn * 8, smem, tid, warpM, warpN, lane, acc);

    // Epilogue: Q -> hi+lo A-frags; K -> hi B-frags; V -> hi VT B-frags.
    const bool isq = (bn < 2);
    const bool isv = (bn >= 4);
    const int bwq = bm * 2 + warpM;
#pragma unroll
    for (int nt = 0; nt < 4; nt++) {
        const int n = bn * 128 + warpN * 32 + nt * 8 + 2 * (lane & 3);
        const float b0 = __ldg(bias + n), b1 = __ldg(bias + n + 1);
        const int head = (n >> 5) & 7;
        const int d0 = n & 31;
        const size_t blkbase = ((size_t)bwq * 8 + head) * 1024;  // u32 units
#pragma unroll
        for (int mt = 0; mt < 4; mt++) {
#pragma unroll
            for (int rr = 0; rr < 2; rr++) {
                float v0 = acc[mt][nt][rr * 2 + 0] + b0;
                float v1 = acc[mt][nt][rr * 2 + 1] + b1;
                if (isq) { v0 *= QKV_SCALE; v1 *= QKV_SCALE; }
                const int gp = mt * 16 + (lane >> 2) + rr * 8;
                if (!isv) {
                    const int frag = (gp >> 4) * 2 + (d0 >> 4);
                    const int reg = rr + 2 * (nt & 1);
                    const size_t off = blkbase + frag * 128 + lane * 4 + reg;
                    if (isq) {
                        uint32_t h, l;
                        split2(v0, v1, h, l);
                        ((uint32_t*)g_qf_hi)[off] = h;
                        ((uint32_t*)g_qf_lo)[off] = l;
                    } else {
                        ((uint32_t*)g_kf_hi)[off] = cvt2(v0, v1);
                    }
                } else {
                    const float p0 = __shfl_xor_sync(0xffffffffu, v0, 4);
                    const float p1 = __shfl_xor_sync(0xffffffffu, v1, 4);
                    const bool odd = (lane >> 2) & 1;
                    const float e0 = odd ? p1 : v0;
                    const float e1 = odd ? v1 : p0;
                    const int dmy = d0 + (odd ? 1 : 0);
                    const int gpe = gp & ~1;
                    const int frag = (dmy >> 4) * 4 + (gpe >> 4);
                    const int lane2 = (dmy & 7) * 4 + ((gpe & 7) >> 1);
                    const int reg = (nt & 1) + 2 * rr;
                    const size_t off = blkbase + frag * 128 + lane2 * 4 + reg;
                    ((uint32_t*)g_vf_hi)[off] = cvt2(e0, e1);
                }
            }
        }
    }
}

// ---------------------------------------------------------------------------
// Kernel 2: attention via mma (R13/R14 verified). One 64-thr block per
// (b,win,head). S = Qh.Kh + Ql.Kh ; O = Ph.Vh + Pl.Vh.
// ---------------------------------------------------------------------------
__global__ __launch_bounds__(64) void attn_kernel(const float* __restrict__ rel_pos) {
    const int blk  = blockIdx.x;
    const int head = blk & 7;
    const int bw   = blk >> 3;
    const int win  = bw & 1023;
    const bool lastH = ((win >> 5) == 31);
    const bool lastW = ((win & 31) == 31);
    const int lane = threadIdx.x & 31;
    const int warp = threadIdx.x >> 5;

    __shared__ float rel_s[240];
    for (int i = threadIdx.x; i < 225; i += 64) rel_s[i] = rel_pos[head * 225 + i];
    __syncthreads();

    const uint4* qh = (const uint4*)g_qf_hi + (size_t)blk * 256;
    const uint4* ql = (const uint4*)g_qf_lo + (size_t)blk * 256;
    const uint4* kh = (const uint4*)g_kf_hi + (size_t)blk * 256;
    const uint4* vh = (const uint4*)g_vf_hi + (size_t)blk * 256;

    float S[2][8][4];
#pragma unroll
    for (int a = 0; a < 2; a++)
#pragma unroll
        for (int b = 0; b < 8; b++)
#pragma unroll
            for (int cR = 0; cR < 4; cR++) S[a][b][cR] = 0.f;

    {
        uint4 Q[2][2], K[4][2];
#pragma unroll
        for (int mt = 0; mt < 2; mt++)
#pragma unroll
            for (int kf = 0; kf < 2; kf++)
                Q[mt][kf] = qh[((2 * warp + mt) * 2 + kf) * 32 + lane];
#pragma unroll
        for (int nf = 0; nf < 4; nf++)
#pragma unroll
            for (int kf = 0; kf < 2; kf++)
                K[nf][kf] = kh[(nf * 2 + kf) * 32 + lane];
#pragma unroll
        for (int kf = 0; kf < 2; kf++)
#pragma unroll
            for (int mt = 0; mt < 2; mt++)
#pragma unroll
                for (int nt = 0; nt < 8; nt++) {
                    const uint4& B = K[nt >> 1][kf];
                    mma_f16(S[mt][nt], (const uint32_t*)&Q[mt][kf],
                            (nt & 1) ? B.y : B.x, (nt & 1) ? B.w : B.z);
                }
        uint4 Q2[2][2];
#pragma unroll
        for (int mt = 0; mt < 2; mt++)
#pragma unroll
            for (int kf = 0; kf < 2; kf++)
                Q2[mt][kf] = ql[((2 * warp + mt) * 2 + kf) * 32 + lane];
#pragma unroll
        for (int kf = 0; kf < 2; kf++)
#pragma unroll
            for (int mt = 0; mt < 2; mt++)
#pragma unroll
                for (int nt = 0; nt < 8; nt++) {
                    const uint4& B = K[nt >> 1][kf];
                    mma_f16(S[mt][nt], (const uint32_t*)&Q2[mt][kf],
                            (nt & 1) ? B.y : B.x, (nt & 1) ? B.w : B.z);
                }
    }

    // bias + mask
#pragma unroll
    for (int mt = 0; mt < 2; mt++) {
        const int p_lo = warp * 32 + mt * 16 + (lane >> 2);
        const int p_hi = p_lo + 8;
        const int pi0 = p_lo >> 3, pj0 = p_lo & 7;
        const int pi1 = p_hi >> 3, pj1 = p_hi & 7;
#pragma unroll
        for (int nt = 0; nt < 8; nt++) {
            const int j0 = nt * 8 + 2 * (lane & 3);
#pragma unroll
            for (int jj = 0; jj < 2; jj++) {
                const int j = j0 + jj;
                const int qi = j >> 3, qj = j & 7;
                float r0 = rel_s[(pi0 - qi + 7) * 15 + (pj0 - qj + 7)];
                float r1 = rel_s[(pi1 - qi + 7) * 15 + (pj1 - qj + 7)];
                float s0 = S[mt][nt][jj] + r0;
                float s1 = S[mt][nt][2 + jj] + r1;
                if ((lastH && ((pi0 < 4) != (qi < 4))) || (lastW && ((pj0 < 4) != (qj < 4))))
                    s0 = -1e30f;
                if ((lastH && ((pi1 < 4) != (qi < 4))) || (lastW && ((pj1 < 4) != (qj < 4))))
                    s1 = -1e30f;
                S[mt][nt][jj] = s0;
                S[mt][nt][2 + jj] = s1;
            }
        }
    }

    // softmax per row
    float O[2][4][4];
#pragma unroll
    for (int a = 0; a < 2; a++)
#pragma unroll
        for (int b = 0; b < 4; b++)
#pragma unroll
            for (int cR = 0; cR < 4; cR++) O[a][b][cR] = 0.f;

    uint32_t Ph[2][4][4], Pl[2][4][4];
#pragma unroll
    for (int mt = 0; mt < 2; mt++) {
        float m0 = -3.0e38f, m1 = -3.0e38f;
#pragma unroll
        for (int nt = 0; nt < 8; nt++) {
            m0 = fmaxf(m0, fmaxf(S[mt][nt][0], S[mt][nt][1]));
            m1 = fmaxf(m1, fmaxf(S[mt][nt][2], S[mt][nt][3]));
        }
        m0 = fmaxf(m0, __shfl_xor_sync(0xffffffffu, m0, 1));
        m0 = fmaxf(m0, __shfl_xor_sync(0xffffffffu, m0, 2));
        m1 = fmaxf(m1, __shfl_xor_sync(0xffffffffu, m1, 1));
        m1 = fmaxf(m1, __shfl_xor_sync(0xffffffffu, m1, 2));
        float s0 = 0.f, s1 = 0.f;
#pragma unroll
        for (int nt = 0; nt < 8; nt++) {
            S[mt][nt][0] = __expf(S[mt][nt][0] - m0);
            S[mt][nt][1] = __expf(S[mt][nt][1] - m0);
            S[mt][nt][2] = __expf(S[mt][nt][2] - m1);
            S[mt][nt][3] = __expf(S[mt][nt][3] - m1);
            s0 += S[mt][nt][0] + S[mt][nt][1];
            s1 += S[mt][nt][2] + S[mt][nt][3];
        }
        s0 += __shfl_xor_sync(0xffffffffu, s0, 1);
        s0 += __shfl_xor_sync(0xffffffffu, s0, 2);
        s1 += __shfl_xor_sync(0xffffffffu, s1, 1);
        s1 += __shfl_xor_sync(0xffffffffu, s1, 2);
        const float i0 = 1.f / s0, i1 = 1.f / s1;
#pragma unroll
        for (int kf = 0; kf < 4; kf++) {
            split2(S[mt][2 * kf][0] * i0, S[mt][2 * kf][1] * i0, Ph[mt][kf][0], Pl[mt][kf][0]);
            split2(S[mt][2 * kf][2] * i1, S[mt][2 * kf][3] * i1, Ph[mt][kf][1], Pl[mt][kf][1]);
            split2(S[mt][2 * kf + 1][0] * i0, S[mt][2 * kf + 1][1] * i0, Ph[mt][kf][2], Pl[mt][kf][2]);
            split2(S[mt][2 * kf + 1][2] * i1, S[mt][2 * kf + 1][3] * i1, Ph[mt][kf][3], Pl[mt][kf][3]);
        }
    }

    {
        uint4 V[2][4];
#pragma unroll
        for (int nf = 0; nf < 2; nf++)
#pragma unroll
            for (int kf = 0; kf < 4; kf++)
                V[nf][kf] = vh[(nf * 4 + kf) * 32 + lane];
#pragma unroll
        for (int kf = 0; kf < 4; kf++)
#pragma unroll
            for (int mt = 0; mt < 2; mt++)
#pragma unroll
                for (int nd = 0; nd < 4; nd++) {
                    const uint4& B = V[nd >> 1][kf];
                    mma_f16(O[mt][nd], Ph[mt][kf],
                            (nd & 1) ? B.y : B.x, (nd & 1) ? B.w : B.z);
                }
#pragma unroll
        for (int kf = 0; kf < 4; kf++)
#pragma unroll
            for (int mt = 0; mt < 2; mt++)
#pragma unroll
                for (int nd = 0; nd < 4; nd++) {
                    const uint4& B = V[nd >> 1][kf];
                    mma_f16(O[mt][nd], Pl[mt][kf],
                            (nd & 1) ? B.y : B.x, (nd & 1) ? B.w : B.z);
                }
    }

    // Epilogue: O -> attn-out A-frags (hi+lo).
#pragma unroll
    for (int mt = 0; mt < 2; mt++) {
        const int tf = bw * 4 + warp * 2 + mt;
#pragma unroll
        for (int nd = 0; nd < 4; nd++) {
            const int ch = head * 32 + nd * 8 + 2 * (lane & 3);
            const int chf = ch >> 4;
            uint32_t h0, l0, h1, l1;
            split2(O[mt][nd][0], O[mt][nd][1], h0, l0);
            split2(O[mt][nd][2], O[mt][nd][3], h1, l1);
            const size_t off = ((size_t)tf * 16 + chf) * 128 + lane * 4 + 2 * (nd & 1);
            ((uint32_t*)g_af_hi)[off]     = h0;
            ((uint32_t*)g_af_hi)[off + 1] = h1;
            ((uint32_t*)g_af_lo)[off]     = l0;
            ((uint32_t*)g_af_lo)[off + 1] = l1;
        }
    }
}

// ---------------------------------------------------------------------------
// Kernel 3: output projection, 2-term pipelined; grid (2, 2048).
// ---------------------------------------------------------------------------
__global__ __launch_bounds__(256)
void out_gemm(const float* __restrict__ bias, float* __restrict__ out) {
    extern __shared__ __align__(16) uint4 smem[];   // 36 KB
    const int tid = threadIdx.x;
    const int bn = blockIdx.x;   // 0..1
    const int bm = blockIdx.y;   // 0..2047
    const int lane = tid & 31;
    const int wid  = tid >> 5;
    const int warpM = wid & 1;
    const int warpN = wid >> 1;  // 0..3

    float acc[4][4][4];
#pragma unroll
    for (int a = 0; a < 4; a++)
#pragma unroll
        for (int b = 0; b < 4; b++)
#pragma unroll
            for (int cR = 0; cR < 4; cR++) acc[a][b][cR] = 0.f;

    GemmPtrs g = { (const char*)g_af_hi, (const char*)g_af_lo,
                   (const char*)g_wof_hi };
    gemm_mainloop(g, bm * 8, bn * 8, smem, tid, warpM, warpN, lane, acc);

#pragma unroll
    for (int mt = 0; mt < 4; mt++) {
#pragma unroll
        for (int rr = 0; rr < 2; rr++) {
            const int gt   = bm * 128 + warpM * 64 + mt * 16 + (lane >> 2) + rr * 8;
            const int gbi  = gt >> 16;
            const int grem = gt & 65535;
            const int gwin = grem >> 6;
            const int gp   = grem & 63;
            const int L  = gwin * 4 + gbi;    // reference's scrambled flatten
            const int a  = L >> 10;
            const int r  = (L >> 5) & 31;
            const int s  = L & 31;
            const int hh  = ((r << 3) + (gp >> 3) + 4) & 255;
            const int wwp = ((s << 3) + (gp & 7) + 4) & 255;
            float* orow = out + ((((size_t)a << 8) + hh) * 256 + wwp) * 256;
#pragma unroll
            for (int nt = 0; nt < 4; nt++) {
                const int n = bn * 128 + warpN * 32 + nt * 8 + 2 * (lane & 3);
                *(float2*)&orow[n] =
                    make_float2(acc[mt][nt][rr * 2 + 0] + __ldg(bias + n),
                                acc[mt][nt][rr * 2 + 1] + __ldg(bias + n + 1));
            }
        }
    }
}

// ---------------------------------------------------------------------------
extern "C" void kernel_launch(void* const* d_in, const int* in_sizes, int n_in,
                              void* d_out, int out_size) {
    const float* x      = (const float*)d_in[0];
    const float* w_qkv  = (const float*)d_in[1];
    const float* b_qkv  = (const float*)d_in[2];
    const float* rel    = (const float*)d_in[3];
    const float* w_out  = (const float*)d_in[4];
    const float* b_out  = (const float*)d_in[5];
    float* out = (float*)d_out;

    __half *wq_hi, *wo_hi;
    cudaGetSymbolAddress((void**)&wq_hi, g_wqf_hi);
    cudaGetSymbolAddress((void**)&wo_hi, g_wof_hi);

    cudaFuncSetAttribute(qkv_gemm, cudaFuncAttributeMaxDynamicSharedMemorySize, 24576);
    cudaFuncSetAttribute(out_gemm, cudaFuncAttributeMaxDynamicSharedMemorySize, 36864);

    cvt_x<<<32768, 256>>>(x);
    cvt_w<<<96, 256>>>(w_qkv, wq_hi);
    cvt_w<<<32, 256>>>(w_out, wo_hi);
    qkv_gemm<<<dim3(6, 2048), 256, 24576>>>(b_qkv);
    attn_kernel<<<32768, 64>>>(rel);
    out_gemm<<<dim3(2, 2048), 256, 36864>>>(b_out, out);
}

// round 16
// speedup vs baseline: 1.8314x; 1.8314x over previous
#include <cuda_runtime.h>
#include <cuda_bf16.h>
#include <cuda_fp16.h>
#include <cstdint>

// ---------------------------------------------------------------------------
// WMSA, b=4, H=W=256, c=256, WS=8, HEAD_DIM=32.
// R16: R14 base (best) with all remaining lo-terms dropped -> pure fp16
// tensor pipeline. qkv/out GEMMs single-term; attention single-term QK / PV.
// Measured error model: each lo-drop adds ~1e-4 in quadrature -> ~2.9e-4.
// 128-thr 4-warp CTAs (the proven shape), R10-style 3-stage cp.async pipe.
// ---------------------------------------------------------------------------

#define QKV_SCALE 0.1767766952966369f   // 32^-0.5

// Fragment arrays (fp16). frag = 256 half = 128 u32 = 32 uint4 = 512 B.
__device__ __align__(16) __half g_xf_hi[67108864];   // x A-frags
__device__ __align__(16) __half g_wqf_hi[196608];    // w_qkv B-frags
__device__ __align__(16) __half g_wof_hi[65536];     // w_out B-frags
__device__ __align__(16) __half g_qf_hi[67108864];   // per blk Q A-frags
__device__ __align__(16) __half g_kf_hi[67108864];   // per blk K B-frags
__device__ __align__(16) __half g_vf_hi[67108864];   // per blk VT B-frags
__device__ __align__(16) __half g_af_hi[67108864];   // attn-out A-frags

// ---------------- helpers ----------------
__device__ __forceinline__ uint32_t smem_u32(const void* p) {
    uint32_t a;
    asm("{ .reg .u64 t; cvta.to.shared.u64 t, %1; cvt.u32.u64 %0, t; }"
        : "=r"(a) : "l"(p));
    return a;
}
__device__ __forceinline__ void mma_f16(float* c, const uint32_t* a,
                                        uint32_t b0, uint32_t b1) {
    asm volatile(
        "mma.sync.aligned.m16n8k16.row.col.f32.f16.f16.f32 "
        "{%0,%1,%2,%3}, {%4,%5,%6,%7}, {%8,%9}, {%0,%1,%2,%3};"
        : "+f"(c[0]), "+f"(c[1]), "+f"(c[2]), "+f"(c[3])
        : "r"(a[0]), "r"(a[1]), "r"(a[2]), "r"(a[3]), "r"(b0), "r"(b1));
}
__device__ __forceinline__ uint32_t cvt2(float a, float b) {
    return (uint32_t)__half_as_ushort(__float2half_rn(a)) |
           ((uint32_t)__half_as_ushort(__float2half_rn(b)) << 16);
}
__device__ __forceinline__ void cp16(uint32_t dst, const void* src) {
    asm volatile("cp.async.cg.shared.global [%0], [%1], 16;" :: "r"(dst), "l"(src));
}

// ---------------------------------------------------------------------------
// cvt_x: gathered (roll+window) tokens -> A-frags.
// ---------------------------------------------------------------------------
__global__ __launch_bounds__(256) void cvt_x(const float* __restrict__ x) {
    const int gid  = blockIdx.x * 256 + threadIdx.x;
    const int lane = gid & 31;
    const int f    = gid >> 5;          // tf*16 + kf
    const int kf   = f & 15, tf = f >> 4;
    const int r    = lane >> 2;
    const int c0   = kf * 16 + 2 * (lane & 3);
    int t = tf * 16 + r;
    const float* row0; const float* row1;
    {
        int bi = t >> 16, rem = t & 65535, win = rem >> 6, p = rem & 63;
        int hh = (((win >> 5) << 3) + (p >> 3) + 4) & 255;
        int ww = (((win & 31) << 3) + (p & 7) + 4) & 255;
        row0 = x + ((((size_t)bi << 8) + hh) * 256 + ww) * 256;
        t += 8;
        bi = t >> 16; rem = t & 65535; win = rem >> 6; p = rem & 63;
        hh = (((win >> 5) << 3) + (p >> 3) + 4) & 255;
        ww = (((win & 31) << 3) + (p & 7) + 4) & 255;
        row1 = x + ((((size_t)bi << 8) + hh) * 256 + ww) * 256;
    }
    float2 v00 = *(const float2*)(row0 + c0);
    float2 v10 = *(const float2*)(row1 + c0);
    float2 v01 = *(const float2*)(row0 + c0 + 8);
    float2 v11 = *(const float2*)(row1 + c0 + 8);
    uint4 h;
    h.x = cvt2(v00.x, v00.y);
    h.y = cvt2(v10.x, v10.y);
    h.z = cvt2(v01.x, v01.y);
    h.w = cvt2(v11.x, v11.y);
    ((uint4*)g_xf_hi)[(size_t)f * 32 + lane] = h;
}

// cvt weights -> B-frags.
__global__ __launch_bounds__(256) void cvt_w(const float* __restrict__ w,
                                             __half* __restrict__ hi) {
    const int gid  = blockIdx.x * 256 + threadIdx.x;
    const int lane = gid & 31;
    const int f    = gid >> 5;          // nf*16 + kf
    const int kf   = f & 15, nf = f >> 4;
    const int r    = lane >> 2;
    const int c0   = kf * 16 + 2 * (lane & 3);
    const float* row0 = w + (size_t)(nf * 16 + r) * 256;
    const float* row1 = row0 + 8 * 256;
    float2 v00 = *(const float2*)(row0 + c0);
    float2 v10 = *(const float2*)(row1 + c0);
    float2 v01 = *(const float2*)(row0 + c0 + 8);
    float2 v11 = *(const float2*)(row1 + c0 + 8);
    uint4 h;
    h.x = cvt2(v00.x, v00.y);
    h.y = cvt2(v10.x, v10.y);
    h.z = cvt2(v01.x, v01.y);
    h.w = cvt2(v11.x, v11.y);
    ((uint4*)hi)[(size_t)f * 32 + lane] = h;
}

// ---------------------------------------------------------------------------
// Single-term pipelined mainloop (both GEMMs). CTA 128 thr, 2x2 warps of
// 64x32. Stage = 12 frags (A 0-7, B 8-11) = 6 KB; 3 stages = 18 KB.
// ---------------------------------------------------------------------------
struct GemmPtrs1 { const char *ah, *bh; };

__device__ __forceinline__ void issue_stage1(const GemmPtrs1& g, int tfb, int nfb,
                                             int kf, uint32_t smem_base, int tid) {
    const int chunk = tid & 31;
    const int g0    = tid >> 5;          // 0..3
    const uint32_t dbase = smem_base + (kf % 3) * 6144 + chunk * 16;
#pragma unroll
    for (int r = 0; r < 3; r++) {
        const int slot = g0 + 4 * r;
        const char* src;
        if (slot < 8)
            src = g.ah + ((size_t)((tfb + slot) * 16 + kf)) * 512 + chunk * 16;
        else
            src = g.bh + ((size_t)((nfb + slot - 8) * 16 + kf)) * 512 + chunk * 16;
        cp16(dbase + slot * 512, src);
    }
    asm volatile("cp.async.commit_group;" ::: "memory");
}

__device__ __forceinline__ void gemm_mainloop1(const GemmPtrs1& g, int tfb, int nfb,
                                               uint4* smem, int tid,
                                               int warpM, int warpN, int lane,
                                               float acc[4][4][4]) {
    const uint32_t smem_base = smem_u32(smem);
    issue_stage1(g, tfb, nfb, 0, smem_base, tid);
    issue_stage1(g, tfb, nfb, 1, smem_base, tid);

#pragma unroll
    for (int kf = 0; kf < 16; kf++) {
        if (kf < 14)
            asm volatile("cp.async.wait_group 1;" ::: "memory");
        else
            asm volatile("cp.async.wait_group 0;" ::: "memory");
        __syncthreads();
        if (kf < 14) issue_stage1(g, tfb, nfb, kf + 2, smem_base, tid);

        const uint4* sb = smem + (kf % 3) * 384;
        uint4 Ah[4], Bh[2];
#pragma unroll
        for (int mt = 0; mt < 4; mt++)
            Ah[mt] = sb[(warpM * 4 + mt) * 32 + lane];
#pragma unroll
        for (int nb = 0; nb < 2; nb++)
            Bh[nb] = sb[256 + (warpN * 2 + nb) * 32 + lane];
#pragma unroll
        for (int mt = 0; mt < 4; mt++)
#pragma unroll
            for (int nt = 0; nt < 4; nt++) {
                const uint4& B = Bh[nt >> 1];
                mma_f16(acc[mt][nt], (const uint32_t*)&Ah[mt],
                        (nt & 1) ? B.y : B.x, (nt & 1) ? B.w : B.z);
            }
    }
}

// ---------------------------------------------------------------------------
// Kernel 1: QKV GEMM (single term). grid (12, 2048).
// ---------------------------------------------------------------------------
__global__ __launch_bounds__(128)
void qkv_gemm(const float* __restrict__ bias) {
    extern __shared__ __align__(16) uint4 smem[];   // 18 KB, 3 stages
    const int tid = threadIdx.x;
    const int bn = blockIdx.x;   // 0..11
    const int bm = blockIdx.y;   // 0..2047
    const int lane = tid & 31;
    const int wid  = tid >> 5;
    const int warpM = wid & 1;
    const int warpN = wid >> 1;

    float acc[4][4][4];
#pragma unroll
    for (int a = 0; a < 4; a++)
#pragma unroll
        for (int b = 0; b < 4; b++)
#pragma unroll
            for (int cR = 0; cR < 4; cR++) acc[a][b][cR] = 0.f;

    GemmPtrs1 g = { (const char*)g_xf_hi, (const char*)g_wqf_hi };
    gemm_mainloop1(g, bm * 8, bn * 4, smem, tid, warpM, warpN, lane, acc);

    // Epilogue: Q -> hi A-frags; K -> hi B-frags; V -> hi VT B-frags.
    const bool isq = (bn < 4);
    const bool isv = (bn >= 8);
    const int bwq = bm * 2 + warpM;
#pragma unroll
    for (int nt = 0; nt < 4; nt++) {
        const int n = bn * 64 + warpN * 32 + nt * 8 + 2 * (lane & 3);
        const float b0 = __ldg(bias + n), b1 = __ldg(bias + n + 1);
        const int head = (n >> 5) & 7;
        const int d0 = n & 31;
        const size_t blkbase = ((size_t)bwq * 8 + head) * 1024;  // u32 units
#pragma unroll
        for (int mt = 0; mt < 4; mt++) {
#pragma unroll
            for (int rr = 0; rr < 2; rr++) {
                float v0 = acc[mt][nt][rr * 2 + 0] + b0;
                float v1 = acc[mt][nt][rr * 2 + 1] + b1;
                if (isq) { v0 *= QKV_SCALE; v1 *= QKV_SCALE; }
                const int gp = mt * 16 + (lane >> 2) + rr * 8;
                if (!isv) {
                    const int frag = (gp >> 4) * 2 + (d0 >> 4);
                    const int reg = rr + 2 * (nt & 1);
                    const size_t off = blkbase + frag * 128 + lane * 4 + reg;
                    if (isq) {
                        ((uint32_t*)g_qf_hi)[off] = cvt2(v0, v1);
                    } else {
                        ((uint32_t*)g_kf_hi)[off] = cvt2(v0, v1);
                    }
                } else {
                    const float p0 = __shfl_xor_sync(0xffffffffu, v0, 4);
                    const float p1 = __shfl_xor_sync(0xffffffffu, v1, 4);
                    const bool odd = (lane >> 2) & 1;
                    const float e0 = odd ? p1 : v0;
                    const float e1 = odd ? v1 : p0;
                    const int dmy = d0 + (odd ? 1 : 0);
                    const int gpe = gp & ~1;
                    const int frag = (dmy >> 4) * 4 + (gpe >> 4);
                    const int lane2 = (dmy & 7) * 4 + ((gpe & 7) >> 1);
                    const int reg = (nt & 1) + 2 * rr;
                    const size_t off = blkbase + frag * 128 + lane2 * 4 + reg;
                    ((uint32_t*)g_vf_hi)[off] = cvt2(e0, e1);
                }
            }
        }
    }
}

// ---------------------------------------------------------------------------
// Kernel 2: attention via mma, pure fp16. One 64-thr block per (b,win,head).
// S = Qh.Kh ; O = Ph.Vh.
// ---------------------------------------------------------------------------
__global__ __launch_bounds__(64) void attn_kernel(const float* __restrict__ rel_pos) {
    const int blk  = blockIdx.x;
    const int head = blk & 7;
    const int bw   = blk >> 3;
    const int win  = bw & 1023;
    const bool lastH = ((win >> 5) == 31);
    const bool lastW = ((win & 31) == 31);
    const int lane = threadIdx.x & 31;
    const int warp = threadIdx.x >> 5;

    __shared__ float rel_s[240];
    for (int i = threadIdx.x; i < 225; i += 64) rel_s[i] = rel_pos[head * 225 + i];
    __syncthreads();

    const uint4* qh = (const uint4*)g_qf_hi + (size_t)blk * 256;
    const uint4* kh = (const uint4*)g_kf_hi + (size_t)blk * 256;
    const uint4* vh = (const uint4*)g_vf_hi + (size_t)blk * 256;

    float S[2][8][4];
#pragma unroll
    for (int a = 0; a < 2; a++)
#pragma unroll
        for (int b = 0; b < 8; b++)
#pragma unroll
            for (int cR = 0; cR < 4; cR++) S[a][b][cR] = 0.f;

    {
        uint4 Q[2][2], K[4][2];
#pragma unroll
        for (int mt = 0; mt < 2; mt++)
#pragma unroll
            for (int kf = 0; kf < 2; kf++)
                Q[mt][kf] = qh[((2 * warp + mt) * 2 + kf) * 32 + lane];
#pragma unroll
        for (int nf = 0; nf < 4; nf++)
#pragma unroll
            for (int kf = 0; kf < 2; kf++)
                K[nf][kf] = kh[(nf * 2 + kf) * 32 + lane];
#pragma unroll
        for (int kf = 0; kf < 2; kf++)
#pragma unroll
            for (int mt = 0; mt < 2; mt++)
#pragma unroll
                for (int nt = 0; nt < 8; nt++) {
                    const uint4& B = K[nt >> 1][kf];
                    mma_f16(S[mt][nt], (const uint32_t*)&Q[mt][kf],
                            (nt & 1) ? B.y : B.x, (nt & 1) ? B.w : B.z);
                }
    }

    // bias + mask
#pragma unroll
    for (int mt = 0; mt < 2; mt++) {
        const int p_lo = warp * 32 + mt * 16 + (lane >> 2);
        const int p_hi = p_lo + 8;
        const int pi0 = p_lo >> 3, pj0 = p_lo & 7;
        const int pi1 = p_hi >> 3, pj1 = p_hi & 7;
#pragma unroll
        for (int nt = 0; nt < 8; nt++) {
            const int j0 = nt * 8 + 2 * (lane & 3);
#pragma unroll
            for (int jj = 0; jj < 2; jj++) {
                const int j = j0 + jj;
                const int qi = j >> 3, qj = j & 7;
                float r0 = rel_s[(pi0 - qi + 7) * 15 + (pj0 - qj + 7)];
                float r1 = rel_s[(pi1 - qi + 7) * 15 + (pj1 - qj + 7)];
                float s0 = S[mt][nt][jj] + r0;
                float s1 = S[mt][nt][2 + jj] + r1;
                if ((lastH && ((pi0 < 4) != (qi < 4))) || (lastW && ((pj0 < 4) != (qj < 4))))
                    s0 = -1e30f;
                if ((lastH && ((pi1 < 4) != (qi < 4))) || (lastW && ((pj1 < 4) != (qj < 4))))
                    s1 = -1e30f;
                S[mt][nt][jj] = s0;
                S[mt][nt][2 + jj] = s1;
            }
        }
    }

    // softmax per row
    float O[2][4][4];
#pragma unroll
    for (int a = 0; a < 2; a++)
#pragma unroll
        for (int b = 0; b < 4; b++)
#pragma unroll
            for (int cR = 0; cR < 4; cR++) O[a][b][cR] = 0.f;

    uint32_t Ph[2][4][4];
#pragma unroll
    for (int mt = 0; mt < 2; mt++) {
        float m0 = -3.0e38f, m1 = -3.0e38f;
#pragma unroll
        for (int nt = 0; nt < 8; nt++) {
            m0 = fmaxf(m0, fmaxf(S[mt][nt][0], S[mt][nt][1]));
            m1 = fmaxf(m1, fmaxf(S[mt][nt][2], S[mt][nt][3]));
        }
        m0 = fmaxf(m0, __shfl_xor_sync(0xffffffffu, m0, 1));
        m0 = fmaxf(m0, __shfl_xor_sync(0xffffffffu, m0, 2));
        m1 = fmaxf(m1, __shfl_xor_sync(0xffffffffu, m1, 1));
        m1 = fmaxf(m1, __shfl_xor_sync(0xffffffffu, m1, 2));
        float s0 = 0.f, s1 = 0.f;
#pragma unroll
        for (int nt = 0; nt < 8; nt++) {
            S[mt][nt][0] = __expf(S[mt][nt][0] - m0);
            S[mt][nt][1] = __expf(S[mt][nt][1] - m0);
            S[mt][nt][2] = __expf(S[mt][nt][2] - m1);
            S[mt][nt][3] = __expf(S[mt][nt][3] - m1);
            s0 += S[mt][nt][0] + S[mt][nt][1];
            s1 += S[mt][nt][2] + S[mt][nt][3];
        }
        s0 += __shfl_xor_sync(0xffffffffu, s0, 1);
        s0 += __shfl_xor_sync(0xffffffffu, s0, 2);
        s1 += __shfl_xor_sync(0xffffffffu, s1, 1);
        s1 += __shfl_xor_sync(0xffffffffu, s1, 2);
        const float i0 = 1.f / s0, i1 = 1.f / s1;
#pragma unroll
        for (int kf = 0; kf < 4; kf++) {
            Ph[mt][kf][0] = cvt2(S[mt][2 * kf][0] * i0, S[mt][2 * kf][1] * i0);
            Ph[mt][kf][1] = cvt2(S[mt][2 * kf][2] * i1, S[mt][2 * kf][3] * i1);
            Ph[mt][kf][2] = cvt2(S[mt][2 * kf + 1][0] * i0, S[mt][2 * kf + 1][1] * i0);
            Ph[mt][kf][3] = cvt2(S[mt][2 * kf + 1][2] * i1, S[mt][2 * kf + 1][3] * i1);
        }
    }

    {
        uint4 V[2][4];
#pragma unroll
        for (int nf = 0; nf < 2; nf++)
#pragma unroll
            for (int kf = 0; kf < 4; kf++)
                V[nf][kf] = vh[(nf * 4 + kf) * 32 + lane];
#pragma unroll
        for (int kf = 0; kf < 4; kf++)
#pragma unroll
            for (int mt = 0; mt < 2; mt++)
#pragma unroll
                for (int nd = 0; nd < 4; nd++) {
                    const uint4& B = V[nd >> 1][kf];
                    mma_f16(O[mt][nd], Ph[mt][kf],
                            (nd & 1) ? B.y : B.x, (nd & 1) ? B.w : B.z);
                }
    }

    // Epilogue: O -> attn-out A-frags (hi only).
#pragma unroll
    for (int mt = 0; mt < 2; mt++) {
        const int tf = bw * 4 + warp * 2 + mt;
#pragma unroll
        for (int nd = 0; nd < 4; nd++) {
            const int ch = head * 32 + nd * 8 + 2 * (lane & 3);
            const int chf = ch >> 4;
            const size_t off = ((size_t)tf * 16 + chf) * 128 + lane * 4 + 2 * (nd & 1);
            ((uint32_t*)g_af_hi)[off]     = cvt2(O[mt][nd][0], O[mt][nd][1]);
            ((uint32_t*)g_af_hi)[off + 1] = cvt2(O[mt][nd][2], O[mt][nd][3]);
        }
    }
}

// ---------------------------------------------------------------------------
// Kernel 3: output projection (single term); grid (4, 2048).
// ---------------------------------------------------------------------------
__global__ __launch_bounds__(128)
void out_gemm(const float* __restrict__ bias, float* __restrict__ out) {
    extern __shared__ __align__(16) uint4 smem[];   // 18 KB
    const int tid = threadIdx.x;
    const int bn = blockIdx.x;   // 0..3
    const int bm = blockIdx.y;   // 0..2047
    const int lane = tid & 31;
    const int wid  = tid >> 5;
    const int warpM = wid & 1;
    const int warpN = wid >> 1;

    float acc[4][4][4];
#pragma unroll
    for (int a = 0; a < 4; a++)
#pragma unroll
        for (int b = 0; b < 4; b++)
#pragma unroll
            for (int cR = 0; cR < 4; cR++) acc[a][b][cR] = 0.f;

    GemmPtrs1 g = { (const char*)g_af_hi, (const char*)g_wof_hi };
    gemm_mainloop1(g, bm * 8, bn * 4, smem, tid, warpM, warpN, lane, acc);

#pragma unroll
    for (int mt = 0; mt < 4; mt++) {
#pragma unroll
        for (int rr = 0; rr < 2; rr++) {
            const int gt   = bm * 128 + warpM * 64 + mt * 16 + (lane >> 2) + rr * 8;
            const int gbi  = gt >> 16;
            const int grem = gt & 65535;
            const int gwin = grem >> 6;
            const int gp   = grem & 63;
            const int L  = gwin * 4 + gbi;    // reference's scrambled flatten
            const int a  = L >> 10;
            const int r  = (L >> 5) & 31;
            const int s  = L & 31;
            const int hh  = ((r << 3) + (gp >> 3) + 4) & 255;
            const int wwp = ((s << 3) + (gp & 7) + 4) & 255;
            float* orow = out + ((((size_t)a << 8) + hh) * 256 + wwp) * 256;
#pragma unroll
            for (int nt = 0; nt < 4; nt++) {
                const int n = bn * 64 + warpN * 32 + nt * 8 + 2 * (lane & 3);
                *(float2*)&orow[n] =
                    make_float2(acc[mt][nt][rr * 2 + 0] + __ldg(bias + n),
                                acc[mt][nt][rr * 2 + 1] + __ldg(bias + n + 1));
            }
        }
    }
}

// ---------------------------------------------------------------------------
extern "C" void kernel_launch(void* const* d_in, const int* in_sizes, int n_in,
                              void* d_out, int out_size) {
    const float* x      = (const float*)d_in[0];
    const float* w_qkv  = (const float*)d_in[1];
    const float* b_qkv  = (const float*)d_in[2];
    const float* rel    = (const float*)d_in[3];
    const float* w_out  = (const float*)d_in[4];
    const float* b_out  = (const float*)d_in[5];
    float* out = (float*)d_out;

    __half *wq_hi, *wo_hi;
    cudaGetSymbolAddress((void**)&wq_hi, g_wqf_hi);
    cudaGetSymbolAddress((void**)&wo_hi, g_wof_hi);

    cudaFuncSetAttribute(qkv_gemm, cudaFuncAttributeMaxDynamicSharedMemorySize, 18432);
    cudaFuncSetAttribute(out_gemm, cudaFuncAttributeMaxDynamicSharedMemorySize, 18432);

    cvt_x<<<32768, 256>>>(x);
    cvt_w<<<96, 256>>>(w_qkv, wq_hi);
    cvt_w<<<32, 256>>>(w_out, wo_hi);
    qkv_gemm<<<dim3(12, 2048), 128, 18432>>>(b_qkv);
    attn_kernel<<<32768, 64>>>(rel);
    out_gemm<<<dim3(4, 2048), 128, 18432>>>(b_out, out);
}